// round 11
// baseline (speedup 1.0000x reference)
#include <cuda_runtime.h>
#include <cstdint>

#define NBATCH 256
#define NTIME  256
#define NS     512   // state size
#define NE     128   // embedding
#define NALPH  128   // alphabet / output
#define FAN    640   // NE + NS
#define BT     (NBATCH * NTIME)

#define NROWT  16    // row tiles (16 batch rows each)
#define NCOLT  8     // col tiles (64 state cols each)
#define BARPAD 32    // ints per barrier counter -> one 128B L2 line each

typedef unsigned long long u64;

// ---- scratch (static __device__: allocation-free per harness rules) ----
// t-major layouts: plane t is a dense 256x512 block (full-sector writes).
__device__ float g_fin[BT * NS];           // fin[(t*NBATCH + b)*NS + n]
__device__ float g_states[BT * NS];        // log[(t*NBATCH + b)*NS + n]
__device__ float g_state[2][NBATCH * NS];  // HOT 1MB ping-pong exchange buffer
__device__ int   g_bar[NTIME * NROWT * BARPAD];

// ---- packed fp32x2 helpers (Blackwell FFMA2) ----
__device__ __forceinline__ void fma2(u64& d, u64 a, u64 b) {
    asm("fma.rn.f32x2 %0, %1, %2, %0;" : "+l"(d) : "l"(a), "l"(b));
}
__device__ __forceinline__ float hadd2(u64 v) {
    float lo, hi;
    asm("mov.b64 {%0,%1}, %2;" : "=f"(lo), "=f"(hi) : "l"(v));
    return lo + hi;
}

// ---- release arrive / acquire poll ----
__device__ __forceinline__ void arrive_release(int* p) {
    asm volatile("red.release.gpu.global.add.u32 [%0], 1;" :: "l"(p) : "memory");
}
__device__ __forceinline__ int ld_acq(const int* p) {
    int v;
    asm volatile("ld.acquire.gpu.global.b32 %0, [%1];" : "=r"(v) : "l"(p) : "memory");
    return v;
}

// =====================================================================
// reset: zero barrier counters (fresh per launch -> graph-replay safe)
// =====================================================================
__global__ void reset_kernel() {
    int i = blockIdx.x * blockDim.x + threadIdx.x;
    if (i < NTIME * NROWT) g_bar[i * BARPAD] = 0;
}

// =====================================================================
// Phase 1: fin (t-major): g_fin[(t*256+b)*NS+n] = emb[w[b][t]] . W_f[n] + b_in[n]
// Tile rows are 64 consecutive t-major indices (same t, 64 b's).
// =====================================================================
__global__ void __launch_bounds__(256)
fin_kernel(const int* __restrict__ w,
           const float* __restrict__ emb,
           const float* __restrict__ W_in,
           const float* __restrict__ b_in) {
    __shared__ int   widx[64];
    __shared__ float As[64 * 36];
    __shared__ float Bs[64 * 33];

    int tid = threadIdx.x;
    int tx = tid & 15, ty = tid >> 4;
    int bt0 = blockIdx.x * 64;      // t-major row base
    int n0  = blockIdx.y * 64;

    if (tid < 64) {
        int rp = bt0 + tid;                       // rp = t*256 + b
        widx[tid] = w[((rp & 255) << 8) | (rp >> 8)];  // w[b*256 + t]
    }
    __syncthreads();

    float acc[4][4] = {};

    for (int kc = 0; kc < NE; kc += 32) {
        for (int s = tid; s < 512; s += 256) {
            int row = s >> 3, q = (s & 7) << 2;
            float4 v = *(const float4*)&emb[widx[row] * NE + kc + q];
            *(float4*)&As[row * 36 + q] = v;
        }
        for (int s = tid; s < 512; s += 256) {
            int row = s >> 3, q = (s & 7) << 2;
            float4 v = *(const float4*)&W_in[(n0 + row) * FAN + kc + q];
            float* d = &Bs[row * 33 + q];
            d[0] = v.x; d[1] = v.y; d[2] = v.z; d[3] = v.w;
        }
        __syncthreads();
        #pragma unroll
        for (int k = 0; k < 32; ++k) {
            float a[4], b[4];
            #pragma unroll
            for (int i = 0; i < 4; ++i) a[i] = As[(ty + 16 * i) * 36 + k];
            #pragma unroll
            for (int j = 0; j < 4; ++j) b[j] = Bs[(tx + 16 * j) * 33 + k];
            #pragma unroll
            for (int i = 0; i < 4; ++i)
                #pragma unroll
                for (int j = 0; j < 4; ++j)
                    acc[i][j] = fmaf(a[i], b[j], acc[i][j]);
        }
        __syncthreads();
    }

    #pragma unroll
    for (int i = 0; i < 4; ++i) {
        int r = bt0 + ty + 16 * i;
        #pragma unroll
        for (int j = 0; j < 4; ++j) {
            int c = n0 + tx + 16 * j;
            g_fin[r * NS + c] = acc[i][j] + b_in[c];
        }
    }
}

// =====================================================================
// Phase 2: persistent recurrent kernel.
// Exchange goes through the 1MB L2-hot ping-pong buffer g_state[t&1];
// the 134MB t-major g_states log is written AFTER the release (streaming,
// dense planes) so cold-DRAM write-allocate never sits on the chain.
// =====================================================================
__global__ void __launch_bounds__(256, 1)
rnn_kernel(const float* __restrict__ W_in) {
    extern __shared__ float sm[];
    float* Bs = sm;                 // [64][516]  W_s slice
    float* As = sm + 64 * 516;      // [16][520]  state tile

    const int tid  = threadIdx.x;
    const int wrp  = tid >> 5;
    const int lane = tid & 31;
    const int tx   = lane & 7;
    const int tyq  = lane >> 3;
    const int rowtile = blockIdx.x >> 3;   // 0..15
    const int coltile = blockIdx.x & 7;    // 0..7
    const int rb0 = rowtile * 16;
    const int cb0 = coltile * 64;

    for (int s = tid; s < 64 * 128; s += 256) {
        int row = s >> 7, q = (s & 127) << 2;
        float4 v = *(const float4*)&W_in[(cb0 + row) * FAN + NE + q];
        *(float4*)&Bs[row * 516 + q] = v;
    }
    __syncthreads();

    const int mycol = 8 * wrp + tx;
    const float* bp  = Bs + mycol * 516;
    const float* ap0 = As + (tyq)      * 520;
    const float* ap1 = As + (tyq + 4)  * 520;
    const float* ap2 = As + (tyq + 8)  * 520;
    const float* ap3 = As + (tyq + 12) * 520;

    const int c  = cb0 + mycol;
    int rr[4];
    rr[0] = rb0 + tyq; rr[1] = rb0 + tyq + 4;
    rr[2] = rb0 + tyq + 8; rr[3] = rb0 + tyq + 12;

    // prefetch fin for t = 0 (t-major plane 0)
    float ffin[4];
    #pragma unroll
    for (int i = 0; i < 4; ++i)
        ffin[i] = __ldcg(&g_fin[(0 * NBATCH + rr[i]) * NS + c]);

    for (int t = 0; t < NTIME; ++t) {
        u64 acc[4] = {};

        if (t > 0) {
            #pragma unroll 4
            for (int k = 0; k < NS; k += 4) {
                ulonglong2 B  = *(const ulonglong2*)(bp  + k);
                ulonglong2 A0 = *(const ulonglong2*)(ap0 + k);
                ulonglong2 A1 = *(const ulonglong2*)(ap1 + k);
                ulonglong2 A2 = *(const ulonglong2*)(ap2 + k);
                ulonglong2 A3 = *(const ulonglong2*)(ap3 + k);
                fma2(acc[0], A0.x, B.x); fma2(acc[0], A0.y, B.y);
                fma2(acc[1], A1.x, B.x); fma2(acc[1], A1.y, B.y);
                fma2(acc[2], A2.x, B.x); fma2(acc[2], A2.y, B.y);
                fma2(acc[3], A3.x, B.x); fma2(acc[3], A3.y, B.y);
            }
        }

        // epilogue: v = tanh(acc + fin_t)
        float v[4];
        #pragma unroll
        for (int i = 0; i < 4; ++i)
            v[i] = tanhf(hadd2(acc[i]) + ffin[i]);

        if (t + 1 < NTIME) {
            // exchange store: HOT 1MB ping-pong buffer (L2 hit, cheap release)
            #pragma unroll
            for (int i = 0; i < 4; ++i)
                g_state[t & 1][rr[i] * NS + c] = v[i];
            __syncthreads();          // CTA h-b: exchange STGs precede release
            if (tid == 0)
                arrive_release(&g_bar[(t * NROWT + rowtile) * BARPAD]);
        }

        // log (dense t-major plane, streaming; OFF the critical path)
        #pragma unroll
        for (int i = 0; i < 4; ++i)
            __stcs(&g_states[((unsigned)t * NBATCH + rr[i]) * NS + c], v[i]);

        if (t + 1 < NTIME) {
            // prefetch fin(t+1) — dense plane, overlaps peers' arrival
            #pragma unroll
            for (int i = 0; i < 4; ++i)
                ffin[i] = __ldcg(&g_fin[((t + 1) * NBATCH + rr[i]) * NS + c]);
            if (tid == 0) {
                const int* bar = &g_bar[(t * NROWT + rowtile) * BARPAD];
                while (ld_acq(bar) < NCOLT) { }
            }
            __syncthreads();

            // stage state[t] from the HOT buffer (L2 hit; __ldcg: no stale L1)
            #pragma unroll
            for (int s = tid; s < 16 * 128; s += 256) {
                int row = s >> 7, q4 = (s & 127) << 2;
                float4 vv = __ldcg((const float4*)
                    &g_state[t & 1][(rb0 + row) * NS + q4]);
                *(float4*)&As[row * 520 + q4] = vv;
            }
            __syncthreads();
        }
    }
}

// =====================================================================
// Phase 3: y[bt][a] = dot(states[b][t], W_out[a]) + b_out[a]
// states is t-major: row bt=b*256+t -> g_states row ((bt&255)<<8)|(bt>>8)
// =====================================================================
__global__ void __launch_bounds__(256)
out_kernel(const float* __restrict__ W_out,
           const float* __restrict__ b_out,
           float* __restrict__ y) {
    __shared__ float As[64 * 36];
    __shared__ float Bs[64 * 33];
    __shared__ int   rowmap[64];

    int tid = threadIdx.x;
    int tx = tid & 15, ty = tid >> 4;
    int bt0 = blockIdx.x * 64;
    int a0  = blockIdx.y * 64;

    if (tid < 64) {
        int r = bt0 + tid;                         // output row (b-major)
        rowmap[tid] = ((r & 255) << 8) | (r >> 8); // t-major states row
    }
    __syncthreads();

    float acc[4][4] = {};

    for (int kc = 0; kc < NS; kc += 32) {
        for (int s = tid; s < 512; s += 256) {
            int row = s >> 3, q = (s & 7) << 2;
            float4 v = *(const float4*)&g_states[rowmap[row] * NS + kc + q];
            *(float4*)&As[row * 36 + q] = v;
        }
        for (int s = tid; s < 512; s += 256) {
            int row = s >> 3, q = (s & 7) << 2;
            float4 v = *(const float4*)&W_out[(a0 + row) * NS + kc + q];
            float* d = &Bs[row * 33 + q];
            d[0] = v.x; d[1] = v.y; d[2] = v.z; d[3] = v.w;
        }
        __syncthreads();
        #pragma unroll
        for (int k = 0; k < 32; ++k) {
            float a[4], b[4];
            #pragma unroll
            for (int i = 0; i < 4; ++i) a[i] = As[(ty + 16 * i) * 36 + k];
            #pragma unroll
            for (int j = 0; j < 4; ++j) b[j] = Bs[(tx + 16 * j) * 33 + k];
            #pragma unroll
            for (int i = 0; i < 4; ++i)
                #pragma unroll
                for (int j = 0; j < 4; ++j)
                    acc[i][j] = fmaf(a[i], b[j], acc[i][j]);
        }
        __syncthreads();
    }

    #pragma unroll
    for (int i = 0; i < 4; ++i) {
        int r = bt0 + ty + 16 * i;
        #pragma unroll
        for (int j = 0; j < 4; ++j) {
            int col = a0 + tx + 16 * j;
            y[r * NALPH + col] = acc[i][j] + b_out[col];
        }
    }
}

// =====================================================================
// launch
// =====================================================================
extern "C" void kernel_launch(void* const* d_in, const int* in_sizes, int n_in,
                              void* d_out, int out_size) {
    const int*   w     = (const int*)  d_in[0];
    const float* emb   = (const float*)d_in[1];
    const float* W_in  = (const float*)d_in[2];
    const float* b_in  = (const float*)d_in[3];
    const float* W_out = (const float*)d_in[4];
    const float* b_out = (const float*)d_in[5];
    float* y = (float*)d_out;

    size_t rnn_smem = (size_t)(64 * 516 + 16 * 520) * sizeof(float);
    cudaFuncSetAttribute(rnn_kernel,
                         cudaFuncAttributeMaxDynamicSharedMemorySize,
                         (int)rnn_smem);

    reset_kernel<<<(NTIME * NROWT + 255) / 256, 256>>>();
    fin_kernel<<<dim3(BT / 64, NS / 64), 256>>>(w, emb, W_in, b_in);
    rnn_kernel<<<128, 256, rnn_smem>>>(W_in);
    out_kernel<<<dim3(BT / 64, NALPH / 64), 256>>>(W_out, b_out, y);
}

// round 12
// speedup vs baseline: 1.0163x; 1.0163x over previous
#include <cuda_runtime.h>
#include <cstdint>

#define NBATCH 256
#define NTIME  256
#define NS     512   // state size
#define NE     128   // embedding
#define NALPH  128   // alphabet / output
#define FAN    640   // NE + NS
#define BT     (NBATCH * NTIME)

#define NROWT  16    // row tiles (16 batch rows each)
#define NCOLT  8     // col tiles (64 state cols each)
#define BARPAD 32    // ints per barrier counter -> one 128B L2 line each

typedef unsigned long long u64;

// ---- scratch (static __device__: allocation-free per harness rules) ----
// t-major layouts: plane t is a dense 256x512 block (full-sector writes).
__device__ float g_fin[BT * NS];           // fin[(t*NBATCH + b)*NS + n]
__device__ float g_states[BT * NS];        // log[(t*NBATCH + b)*NS + n]
__device__ float g_state[2][NBATCH * NS];  // HOT 1MB ping-pong exchange buffer
__device__ int   g_bar[NTIME * NROWT * BARPAD];

// ---- packed fp32x2 helpers (Blackwell FFMA2) ----
__device__ __forceinline__ void fma2(u64& d, u64 a, u64 b) {
    asm("fma.rn.f32x2 %0, %1, %2, %0;" : "+l"(d) : "l"(a), "l"(b));
}
__device__ __forceinline__ float hadd2(u64 v) {
    float lo, hi;
    asm("mov.b64 {%0,%1}, %2;" : "=f"(lo), "=f"(hi) : "l"(v));
    return lo + hi;
}
__device__ __forceinline__ float tanh_fast(float x) {
    float y;
    asm("tanh.approx.f32 %0, %1;" : "=f"(y) : "f"(x));
    return y;
}

// ---- release arrive / acquire poll ----
__device__ __forceinline__ void arrive_release(int* p) {
    asm volatile("red.release.gpu.global.add.u32 [%0], 1;" :: "l"(p) : "memory");
}
__device__ __forceinline__ int ld_acq(const int* p) {
    int v;
    asm volatile("ld.acquire.gpu.global.b32 %0, [%1];" : "=r"(v) : "l"(p) : "memory");
    return v;
}

// =====================================================================
// reset + dummy (dummy positions rnn_kernel as the 4th launch => ncu
// profiles it instead of out_kernel)
// =====================================================================
__global__ void reset_kernel() {
    int i = blockIdx.x * blockDim.x + threadIdx.x;
    if (i < NTIME * NROWT) g_bar[i * BARPAD] = 0;
}
__global__ void dummy_kernel() {}

// =====================================================================
// Phase 1: fin (t-major): g_fin[(t*256+b)*NS+n] = emb[w[b][t]] . W_f[n] + b_in[n]
// =====================================================================
__global__ void __launch_bounds__(256)
fin_kernel(const int* __restrict__ w,
           const float* __restrict__ emb,
           const float* __restrict__ W_in,
           const float* __restrict__ b_in) {
    __shared__ int   widx[64];
    __shared__ float As[64 * 36];
    __shared__ float Bs[64 * 33];

    int tid = threadIdx.x;
    int tx = tid & 15, ty = tid >> 4;
    int bt0 = blockIdx.x * 64;      // t-major row base
    int n0  = blockIdx.y * 64;

    if (tid < 64) {
        int rp = bt0 + tid;                            // rp = t*256 + b
        widx[tid] = w[((rp & 255) << 8) | (rp >> 8)];  // w[b*256 + t]
    }
    __syncthreads();

    float acc[4][4] = {};

    for (int kc = 0; kc < NE; kc += 32) {
        for (int s = tid; s < 512; s += 256) {
            int row = s >> 3, q = (s & 7) << 2;
            float4 v = *(const float4*)&emb[widx[row] * NE + kc + q];
            *(float4*)&As[row * 36 + q] = v;
        }
        for (int s = tid; s < 512; s += 256) {
            int row = s >> 3, q = (s & 7) << 2;
            float4 v = *(const float4*)&W_in[(n0 + row) * FAN + kc + q];
            float* d = &Bs[row * 33 + q];
            d[0] = v.x; d[1] = v.y; d[2] = v.z; d[3] = v.w;
        }
        __syncthreads();
        #pragma unroll
        for (int k = 0; k < 32; ++k) {
            float a[4], b[4];
            #pragma unroll
            for (int i = 0; i < 4; ++i) a[i] = As[(ty + 16 * i) * 36 + k];
            #pragma unroll
            for (int j = 0; j < 4; ++j) b[j] = Bs[(tx + 16 * j) * 33 + k];
            #pragma unroll
            for (int i = 0; i < 4; ++i)
                #pragma unroll
                for (int j = 0; j < 4; ++j)
                    acc[i][j] = fmaf(a[i], b[j], acc[i][j]);
        }
        __syncthreads();
    }

    #pragma unroll
    for (int i = 0; i < 4; ++i) {
        int r = bt0 + ty + 16 * i;
        #pragma unroll
        for (int j = 0; j < 4; ++j) {
            int c = n0 + tx + 16 * j;
            g_fin[r * NS + c] = acc[i][j] + b_in[c];
        }
    }
}

// =====================================================================
// Phase 2: persistent recurrent kernel.
// Step pipeline (per iter t>0): all-thread acquire-poll of flag(t-1),
// 8 LDGs up front from the hot ping-pong buffer, STS/GEMM in two k-halves
// (half-2's L2 latency hidden under half-1's GEMM). tanh.approx epilogue.
// =====================================================================
__global__ void __launch_bounds__(256, 1)
rnn_kernel(const float* __restrict__ W_in) {
    extern __shared__ float sm[];
    float* Bs = sm;                 // [64][516]  W_s slice
    float* As = sm + 64 * 516;      // [16][520]  state tile

    const int tid  = threadIdx.x;
    const int wrp  = tid >> 5;
    const int lane = tid & 31;
    const int tx   = lane & 7;
    const int tyq  = lane >> 3;
    const int rowtile = blockIdx.x >> 3;   // 0..15
    const int coltile = blockIdx.x & 7;    // 0..7
    const int rb0 = rowtile * 16;
    const int cb0 = coltile * 64;

    for (int s = tid; s < 64 * 128; s += 256) {
        int row = s >> 7, q = (s & 127) << 2;
        float4 v = *(const float4*)&W_in[(cb0 + row) * FAN + NE + q];
        *(float4*)&Bs[row * 516 + q] = v;
    }
    __syncthreads();

    const int mycol = 8 * wrp + tx;
    const float* bp  = Bs + mycol * 516;
    const float* ap0 = As + (tyq)      * 520;
    const float* ap1 = As + (tyq + 4)  * 520;
    const float* ap2 = As + (tyq + 8)  * 520;
    const float* ap3 = As + (tyq + 12) * 520;

    const int c  = cb0 + mycol;
    int rr[4];
    rr[0] = rb0 + tyq; rr[1] = rb0 + tyq + 4;
    rr[2] = rb0 + tyq + 8; rr[3] = rb0 + tyq + 12;

    // staging mapping: per thread, 4 float4 per k-half
    const int srow = tid >> 4;           // 0..15
    const int sc   = (tid & 15) << 2;    // 0..60

    // prefetch fin for t = 0
    float ffin[4];
    #pragma unroll
    for (int i = 0; i < 4; ++i)
        ffin[i] = __ldcg(&g_fin[(0 * NBATCH + rr[i]) * NS + c]);

    for (int t = 0; t < NTIME; ++t) {
        u64 acc[4] = {};

        if (t > 0) {
            // ---- all-thread acquire poll (1 coalesced req/warp) ----
            const int* bar = &g_bar[((t - 1) * NROWT + rowtile) * BARPAD];
            while (ld_acq(bar) < NCOLT) { }

            // ---- issue all staging LDGs up front (hot L2 buffer) ----
            const float* srcrow = &g_state[(t - 1) & 1][(rb0 + srow) * NS];
            float4 p0[4], p1[4];
            #pragma unroll
            for (int j = 0; j < 4; ++j)
                p0[j] = __ldcg((const float4*)(srcrow + sc + 64 * j));
            #pragma unroll
            for (int j = 0; j < 4; ++j)
                p1[j] = __ldcg((const float4*)(srcrow + 256 + sc + 64 * j));

            // ---- half 1: STS, sync, GEMM k in [0,256) ----
            float* dstrow = &As[srow * 520];
            #pragma unroll
            for (int j = 0; j < 4; ++j)
                *(float4*)(dstrow + sc + 64 * j) = p0[j];
            __syncthreads();
            #pragma unroll 4
            for (int k = 0; k < 256; k += 4) {
                ulonglong2 B  = *(const ulonglong2*)(bp  + k);
                ulonglong2 A0 = *(const ulonglong2*)(ap0 + k);
                ulonglong2 A1 = *(const ulonglong2*)(ap1 + k);
                ulonglong2 A2 = *(const ulonglong2*)(ap2 + k);
                ulonglong2 A3 = *(const ulonglong2*)(ap3 + k);
                fma2(acc[0], A0.x, B.x); fma2(acc[0], A0.y, B.y);
                fma2(acc[1], A1.x, B.x); fma2(acc[1], A1.y, B.y);
                fma2(acc[2], A2.x, B.x); fma2(acc[2], A2.y, B.y);
                fma2(acc[3], A3.x, B.x); fma2(acc[3], A3.y, B.y);
            }

            // ---- half 2: STS (data arrived during half-1 GEMM), sync, GEMM ----
            #pragma unroll
            for (int j = 0; j < 4; ++j)
                *(float4*)(dstrow + 256 + sc + 64 * j) = p1[j];
            __syncthreads();
            #pragma unroll 4
            for (int k = 256; k < 512; k += 4) {
                ulonglong2 B  = *(const ulonglong2*)(bp  + k);
                ulonglong2 A0 = *(const ulonglong2*)(ap0 + k);
                ulonglong2 A1 = *(const ulonglong2*)(ap1 + k);
                ulonglong2 A2 = *(const ulonglong2*)(ap2 + k);
                ulonglong2 A3 = *(const ulonglong2*)(ap3 + k);
                fma2(acc[0], A0.x, B.x); fma2(acc[0], A0.y, B.y);
                fma2(acc[1], A1.x, B.x); fma2(acc[1], A1.y, B.y);
                fma2(acc[2], A2.x, B.x); fma2(acc[2], A2.y, B.y);
                fma2(acc[3], A3.x, B.x); fma2(acc[3], A3.y, B.y);
            }
        }

        // ---- epilogue: v = tanh(acc + fin_t) ----
        float v[4];
        #pragma unroll
        for (int i = 0; i < 4; ++i)
            v[i] = tanh_fast(hadd2(acc[i]) + ffin[i]);

        // exchange store into HOT ping-pong buffer
        #pragma unroll
        for (int i = 0; i < 4; ++i)
            g_state[t & 1][rr[i] * NS + c] = v[i];
        __syncthreads();   // CTA h-b: exchange STGs (and As reads) done

        if (t + 1 < NTIME) {
            if (tid == 0)
                arrive_release(&g_bar[(t * NROWT + rowtile) * BARPAD]);
        }

        // log (dense t-major plane, streaming; off the critical path)
        #pragma unroll
        for (int i = 0; i < 4; ++i)
            __stcs(&g_states[((unsigned)t * NBATCH + rr[i]) * NS + c], v[i]);

        if (t + 1 < NTIME) {
            // prefetch fin(t+1): overlaps peers' arrival (poll is next iter)
            #pragma unroll
            for (int i = 0; i < 4; ++i)
                ffin[i] = __ldcg(&g_fin[((t + 1) * NBATCH + rr[i]) * NS + c]);
        }
    }
}

// =====================================================================
// Phase 3: y[bt][a] = dot(states[b][t], W_out[a]) + b_out[a]
// states is t-major: row bt=b*256+t -> g_states row ((bt&255)<<8)|(bt>>8)
// =====================================================================
__global__ void __launch_bounds__(256)
out_kernel(const float* __restrict__ W_out,
           const float* __restrict__ b_out,
           float* __restrict__ y) {
    __shared__ float As[64 * 36];
    __shared__ float Bs[64 * 33];
    __shared__ int   rowmap[64];

    int tid = threadIdx.x;
    int tx = tid & 15, ty = tid >> 4;
    int bt0 = blockIdx.x * 64;
    int a0  = blockIdx.y * 64;

    if (tid < 64) {
        int r = bt0 + tid;
        rowmap[tid] = ((r & 255) << 8) | (r >> 8);
    }
    __syncthreads();

    float acc[4][4] = {};

    for (int kc = 0; kc < NS; kc += 32) {
        for (int s = tid; s < 512; s += 256) {
            int row = s >> 3, q = (s & 7) << 2;
            float4 v = *(const float4*)&g_states[rowmap[row] * NS + kc + q];
            *(float4*)&As[row * 36 + q] = v;
        }
        for (int s = tid; s < 512; s += 256) {
            int row = s >> 3, q = (s & 7) << 2;
            float4 v = *(const float4*)&W_out[(a0 + row) * NS + kc + q];
            float* d = &Bs[row * 33 + q];
            d[0] = v.x; d[1] = v.y; d[2] = v.z; d[3] = v.w;
        }
        __syncthreads();
        #pragma unroll
        for (int k = 0; k < 32; ++k) {
            float a[4], b[4];
            #pragma unroll
            for (int i = 0; i < 4; ++i) a[i] = As[(ty + 16 * i) * 36 + k];
            #pragma unroll
            for (int j = 0; j < 4; ++j) b[j] = Bs[(tx + 16 * j) * 33 + k];
            #pragma unroll
            for (int i = 0; i < 4; ++i)
                #pragma unroll
                for (int j = 0; j < 4; ++j)
                    acc[i][j] = fmaf(a[i], b[j], acc[i][j]);
        }
        __syncthreads();
    }

    #pragma unroll
    for (int i = 0; i < 4; ++i) {
        int r = bt0 + ty + 16 * i;
        #pragma unroll
        for (int j = 0; j < 4; ++j) {
            int col = a0 + tx + 16 * j;
            y[r * NALPH + col] = acc[i][j] + b_out[col];
        }
    }
}

// =====================================================================
// launch: reset, fin, dummy, rnn, out  (rnn = 4th launch -> gets profiled)
// =====================================================================
extern "C" void kernel_launch(void* const* d_in, const int* in_sizes, int n_in,
                              void* d_out, int out_size) {
    const int*   w     = (const int*)  d_in[0];
    const float* emb   = (const float*)d_in[1];
    const float* W_in  = (const float*)d_in[2];
    const float* b_in  = (const float*)d_in[3];
    const float* W_out = (const float*)d_in[4];
    const float* b_out = (const float*)d_in[5];
    float* y = (float*)d_out;

    size_t rnn_smem = (size_t)(64 * 516 + 16 * 520) * sizeof(float);
    cudaFuncSetAttribute(rnn_kernel,
                         cudaFuncAttributeMaxDynamicSharedMemorySize,
                         (int)rnn_smem);

    reset_kernel<<<(NTIME * NROWT + 255) / 256, 256>>>();
    fin_kernel<<<dim3(BT / 64, NS / 64), 256>>>(w, emb, W_in, b_in);
    dummy_kernel<<<1, 32>>>();
    rnn_kernel<<<128, 256, rnn_smem>>>(W_in);
    out_kernel<<<dim3(BT / 64, NALPH / 64), 256>>>(W_out, b_out, y);
}

// round 13
// speedup vs baseline: 1.7413x; 1.7134x over previous
#include <cuda_runtime.h>
#include <cstdint>

#define NBATCH 256
#define NTIME  256
#define NS     512
#define NE     128
#define NALPH  128
#define FAN    640
#define BT     (NBATCH * NTIME)

#define NROWT  16
#define NCOLT  8
#define BARPAD 32
#define PITCH  260    // u64 per row in Aq/Bq (bank-conflict-free for frag loads)

typedef unsigned long long u64;
typedef unsigned int u32;

// ---- scratch ----
__device__ float g_fin[BT * NS];          // fin[(t*NBATCH+b)*NS + n]  (t-major)
__device__ float g_states[BT * NS];       // log[(t*NBATCH+b)*NS + n]  (t-major)
__device__ u64   g_state_pk[2][NBATCH * 256];  // HOT packed {hi2,lo2} bf16 k-pairs
__device__ int   g_bar[NTIME * NROWT * BARPAD];

// ---- helpers ----
__device__ __forceinline__ float tanh_fast(float x) {
    float y; asm("tanh.approx.f32 %0, %1;" : "=f"(y) : "f"(x)); return y;
}
__device__ __forceinline__ void arrive_release(int* p) {
    asm volatile("red.release.gpu.global.add.u32 [%0], 1;" :: "l"(p) : "memory");
}
__device__ __forceinline__ int ld_acq(const int* p) {
    int v; asm volatile("ld.acquire.gpu.global.b32 %0, [%1];" : "=r"(v) : "l"(p) : "memory");
    return v;
}

// pack two floats into {hi: bf16(v0),bf16(v1)} low u32, {lo: residual pair} high u32
__device__ __forceinline__ u64 pack_hl(float v0, float v1) {
    u32 hi, lo;
    asm("cvt.rn.bf16x2.f32 %0, %1, %2;" : "=r"(hi) : "f"(v1), "f"(v0));
    float h0, h1;
    asm("{.reg .b16 x,y;\n\t mov.b32 {x,y}, %2;\n\t cvt.f32.bf16 %0, x;\n\t cvt.f32.bf16 %1, y;}"
        : "=f"(h0), "=f"(h1) : "r"(hi));
    asm("cvt.rn.bf16x2.f32 %0, %1, %2;" : "=r"(lo) : "f"(v1 - h1), "f"(v0 - h0));
    return ((u64)lo << 32) | (u64)hi;
}

// D(16x8,f32) += A(16x16,bf16,row) * B(16x8,bf16,col)
__device__ __forceinline__ void mma_bf16(float& d0, float& d1, float& d2, float& d3,
                                         u32 a0, u32 a1, u32 a2, u32 a3,
                                         u32 b0, u32 b1) {
    asm volatile("mma.sync.aligned.m16n8k16.row.col.f32.bf16.bf16.f32 "
                 "{%0,%1,%2,%3}, {%4,%5,%6,%7}, {%8,%9}, {%0,%1,%2,%3};"
                 : "+f"(d0), "+f"(d1), "+f"(d2), "+f"(d3)
                 : "r"(a0), "r"(a1), "r"(a2), "r"(a3), "r"(b0), "r"(b1));
}

// =====================================================================
__global__ void reset_kernel() {
    int i = blockIdx.x * blockDim.x + threadIdx.x;
    if (i < NTIME * NROWT) g_bar[i * BARPAD] = 0;
}
__global__ void dummy_kernel() {}

// =====================================================================
// Phase 1: fin (t-major)
// =====================================================================
__global__ void __launch_bounds__(256)
fin_kernel(const int* __restrict__ w,
           const float* __restrict__ emb,
           const float* __restrict__ W_in,
           const float* __restrict__ b_in) {
    __shared__ int   widx[64];
    __shared__ float As[64 * 36];
    __shared__ float Bs[64 * 33];

    int tid = threadIdx.x;
    int tx = tid & 15, ty = tid >> 4;
    int bt0 = blockIdx.x * 64;
    int n0  = blockIdx.y * 64;

    if (tid < 64) {
        int rp = bt0 + tid;                            // t*256 + b
        widx[tid] = w[((rp & 255) << 8) | (rp >> 8)];  // w[b*256+t]
    }
    __syncthreads();

    float acc[4][4] = {};
    for (int kc = 0; kc < NE; kc += 32) {
        for (int s = tid; s < 512; s += 256) {
            int row = s >> 3, q = (s & 7) << 2;
            float4 v = *(const float4*)&emb[widx[row] * NE + kc + q];
            *(float4*)&As[row * 36 + q] = v;
        }
        for (int s = tid; s < 512; s += 256) {
            int row = s >> 3, q = (s & 7) << 2;
            float4 v = *(const float4*)&W_in[(n0 + row) * FAN + kc + q];
            float* d = &Bs[row * 33 + q];
            d[0] = v.x; d[1] = v.y; d[2] = v.z; d[3] = v.w;
        }
        __syncthreads();
        #pragma unroll
        for (int k = 0; k < 32; ++k) {
            float a[4], b[4];
            #pragma unroll
            for (int i = 0; i < 4; ++i) a[i] = As[(ty + 16 * i) * 36 + k];
            #pragma unroll
            for (int j = 0; j < 4; ++j) b[j] = Bs[(tx + 16 * j) * 33 + k];
            #pragma unroll
            for (int i = 0; i < 4; ++i)
                #pragma unroll
                for (int j = 0; j < 4; ++j)
                    acc[i][j] = fmaf(a[i], b[j], acc[i][j]);
        }
        __syncthreads();
    }
    #pragma unroll
    for (int i = 0; i < 4; ++i) {
        int r = bt0 + ty + 16 * i;
        #pragma unroll
        for (int j = 0; j < 4; ++j) {
            int c = n0 + tx + 16 * j;
            g_fin[r * NS + c] = acc[i][j] + b_in[c];
        }
    }
}

// =====================================================================
// Phase 2: persistent recurrent kernel, tensor-core GEMM.
// 128 CTAs (rowtile = bid>>3: 16 rows; coltile = bid&7: 64 cols), 256 thr.
// Warp w computes D[16 x 8] for cols [8w,8w+8) via mma.m16n8k16 bf16,
// 3-term hi/lo split (~fp32 accuracy). W_s packed once in smem; state
// exchanged as packed u64 k-pairs through the hot 1MB ping-pong buffer.
// =====================================================================
__global__ void __launch_bounds__(256, 1)
rnn_kernel(const float* __restrict__ W_in) {
    extern __shared__ u64 smq[];
    u64* Bq = smq;                 // [64][PITCH]  W_s packed
    u64* Aq = smq + 64 * PITCH;    // [16][PITCH]  state packed

    const int tid  = threadIdx.x;
    const int wrp  = tid >> 5;
    const int lane = tid & 31;
    const int g    = lane >> 2;    // 0..7
    const int tq   = lane & 3;     // 0..3
    const int rowtile = blockIdx.x >> 3;
    const int coltile = blockIdx.x & 7;
    const int rb0 = rowtile * 16;
    const int cb0 = coltile * 64;

    // pack W_s slice once: Bq[n][p] = {hi,lo} of (W[2p], W[2p+1])
    for (int s = tid; s < 64 * 256; s += 256) {
        int n = s >> 8, p = s & 255;
        const float* wp = &W_in[(cb0 + n) * FAN + NE + 2 * p];
        Bq[n * PITCH + p] = pack_hl(wp[0], wp[1]);
    }
    __syncthreads();

    const u64* arow0 = Aq + g * PITCH;
    const u64* arow1 = Aq + (g + 8) * PITCH;
    const u64* brow  = Bq + (8 * wrp + g) * PITCH;

    const int r0 = rb0 + g, r1 = rb0 + g + 8;
    const int c0 = cb0 + 8 * wrp + 2 * tq;     // even col; thread owns c0,c0+1
    const int pg = c0 >> 1;                    // its global k-pair index

    // staging map: strided so STS.64 lanes hit distinct banks
    const int srow = tid >> 4;                 // 0..15
    const int sp0  = tid & 15;

    float2 f0 = *(const float2*)&g_fin[r0 * NS + c0];   // fin t=0
    float2 f1 = *(const float2*)&g_fin[r1 * NS + c0];

    for (int t = 0; t < NTIME; ++t) {
        float d0 = 0.f, d1 = 0.f, d2 = 0.f, d3 = 0.f;

        if (t > 0) {
            const int* bar = &g_bar[((t - 1) * NROWT + rowtile) * BARPAD];
            while (ld_acq(bar) < NCOLT) { }

            // stage packed state[t-1] rows (hot L2 buffer)
            const u64* src = &g_state_pk[(t - 1) & 1][(rb0 + srow) << 8];
            u64* dst = &Aq[srow * PITCH];
            #pragma unroll
            for (int j = 0; j < 16; ++j)
                dst[sp0 + 16 * j] = __ldcg(&src[sp0 + 16 * j]);
            __syncthreads();

            // GEMM: 32 chunks of k16, 3 bf16 MMAs each
            #pragma unroll 4
            for (int c = 0; c < 32; ++c) {
                int p0 = 8 * c + tq, p1 = p0 + 4;
                u64 qa0 = arow0[p0], qa1 = arow1[p0];
                u64 qa2 = arow0[p1], qa3 = arow1[p1];
                u64 qb0 = brow[p0],  qb1 = brow[p1];
                u32 ah0 = (u32)qa0, ah1 = (u32)qa1, ah2 = (u32)qa2, ah3 = (u32)qa3;
                u32 al0 = (u32)(qa0 >> 32), al1 = (u32)(qa1 >> 32);
                u32 al2 = (u32)(qa2 >> 32), al3 = (u32)(qa3 >> 32);
                u32 bh0 = (u32)qb0, bh1 = (u32)qb1;
                u32 bl0 = (u32)(qb0 >> 32), bl1 = (u32)(qb1 >> 32);
                mma_bf16(d0, d1, d2, d3, ah0, ah1, ah2, ah3, bh0, bh1);
                mma_bf16(d0, d1, d2, d3, al0, al1, al2, al3, bh0, bh1);
                mma_bf16(d0, d1, d2, d3, ah0, ah1, ah2, ah3, bl0, bl1);
            }
        }

        // epilogue: v = tanh(acc + fin)   D layout: d0=(r0,c0) d1=(r0,c0+1)
        float v0 = tanh_fast(d0 + f0.x);
        float v1 = tanh_fast(d1 + f0.y);
        float v2 = tanh_fast(d2 + f1.x);
        float v3 = tanh_fast(d3 + f1.y);

        // exchange: pack own k-pair, store to hot buffer
        const int sel = t & 1;
        g_state_pk[sel][(r0 << 8) + pg] = pack_hl(v0, v1);
        g_state_pk[sel][(r1 << 8) + pg] = pack_hl(v2, v3);
        __syncthreads();   // CTA h-b: exchange STGs done, Aq reads done

        if (t + 1 < NTIME) {
            if (tid == 0)
                arrive_release(&g_bar[(t * NROWT + rowtile) * BARPAD]);
        }

        // fp32 log (t-major dense plane, streaming; off critical path)
        float2 o0 = make_float2(v0, v1), o1 = make_float2(v2, v3);
        __stcs((float2*)&g_states[((unsigned)t * NBATCH + r0) * NS + c0], o0);
        __stcs((float2*)&g_states[((unsigned)t * NBATCH + r1) * NS + c0], o1);

        if (t + 1 < NTIME) {
            f0 = __ldcg((const float2*)&g_fin[((t + 1) * NBATCH + r0) * NS + c0]);
            f1 = __ldcg((const float2*)&g_fin[((t + 1) * NBATCH + r1) * NS + c0]);
        }
    }
}

// =====================================================================
// Phase 3: y = states @ W_out^T + b_out   (states t-major)
// =====================================================================
__global__ void __launch_bounds__(256)
out_kernel(const float* __restrict__ W_out,
           const float* __restrict__ b_out,
           float* __restrict__ y) {
    __shared__ float As[64 * 36];
    __shared__ float Bs[64 * 33];
    __shared__ int   rowmap[64];

    int tid = threadIdx.x;
    int tx = tid & 15, ty = tid >> 4;
    int bt0 = blockIdx.x * 64;
    int a0  = blockIdx.y * 64;

    if (tid < 64) {
        int r = bt0 + tid;
        rowmap[tid] = ((r & 255) << 8) | (r >> 8);
    }
    __syncthreads();

    float acc[4][4] = {};
    for (int kc = 0; kc < NS; kc += 32) {
        for (int s = tid; s < 512; s += 256) {
            int row = s >> 3, q = (s & 7) << 2;
            float4 v = *(const float4*)&g_states[rowmap[row] * NS + kc + q];
            *(float4*)&As[row * 36 + q] = v;
        }
        for (int s = tid; s < 512; s += 256) {
            int row = s >> 3, q = (s & 7) << 2;
            float4 v = *(const float4*)&W_out[(a0 + row) * NS + kc + q];
            float* d = &Bs[row * 33 + q];
            d[0] = v.x; d[1] = v.y; d[2] = v.z; d[3] = v.w;
        }
        __syncthreads();
        #pragma unroll
        for (int k = 0; k < 32; ++k) {
            float a[4], b[4];
            #pragma unroll
            for (int i = 0; i < 4; ++i) a[i] = As[(ty + 16 * i) * 36 + k];
            #pragma unroll
            for (int j = 0; j < 4; ++j) b[j] = Bs[(tx + 16 * j) * 33 + k];
            #pragma unroll
            for (int i = 0; i < 4; ++i)
                #pragma unroll
                for (int j = 0; j < 4; ++j)
                    acc[i][j] = fmaf(a[i], b[j], acc[i][j]);
        }
        __syncthreads();
    }
    #pragma unroll
    for (int i = 0; i < 4; ++i) {
        int r = bt0 + ty + 16 * i;
        #pragma unroll
        for (int j = 0; j < 4; ++j) {
            int col = a0 + tx + 16 * j;
            y[r * NALPH + col] = acc[i][j] + b_out[col];
        }
    }
}

// =====================================================================
// launch: reset, fin, dummy, rnn, out
// =====================================================================
extern "C" void kernel_launch(void* const* d_in, const int* in_sizes, int n_in,
                              void* d_out, int out_size) {
    const int*   w     = (const int*)  d_in[0];
    const float* emb   = (const float*)d_in[1];
    const float* W_in  = (const float*)d_in[2];
    const float* b_in  = (const float*)d_in[3];
    const float* W_out = (const float*)d_in[4];
    const float* b_out = (const float*)d_in[5];
    float* y = (float*)d_out;

    size_t rnn_smem = (size_t)(64 + 16) * PITCH * sizeof(u64);   // ~166 KB
    cudaFuncSetAttribute(rnn_kernel,
                         cudaFuncAttributeMaxDynamicSharedMemorySize,
                         (int)rnn_smem);

    reset_kernel<<<(NTIME * NROWT + 255) / 256, 256>>>();
    fin_kernel<<<dim3(BT / 64, NS / 64), 256>>>(w, emb, W_in, b_in);
    dummy_kernel<<<1, 32>>>();
    rnn_kernel<<<128, 256, rnn_smem>>>(W_in);
    out_kernel<<<dim3(BT / 64, NALPH / 64), 256>>>(W_out, b_out, y);
}

// round 14
// speedup vs baseline: 2.0214x; 1.1609x over previous
#include <cuda_runtime.h>
#include <cstdint>

#define NBATCH 256
#define NTIME  256
#define NS     512
#define NE     128
#define NALPH  128
#define FAN    640
#define BT     (NBATCH * NTIME)

#define NROWT  16
#define NCOLT  8
#define BARPAD 32
#define PITCH  264    // u64 per row (16B-chunk phase spread: 132 mod 8 == 4)

// fragment-pair permutation: k-pair p -> smem slot (pairs p, p+4 adjacent)
#define PERM(p) (((p) & 248) | (((p) & 3) << 1) | (((p) >> 2) & 1))

typedef unsigned long long u64;
typedef unsigned int u32;

// ---- scratch ----
__device__ float g_fin[BT * NS];              // fin[(t*NBATCH+b)*NS + n]
__device__ float g_states[BT * NS];           // log[(t*NBATCH+b)*NS + n]
__device__ u64   g_state_pk[2][NBATCH * 256]; // HOT packed {hi,lo} bf16 k-pairs
__device__ int   g_bar[NTIME * NROWT * BARPAD];

// ---- helpers ----
__device__ __forceinline__ float tanh_fast(float x) {
    float y; asm("tanh.approx.f32 %0, %1;" : "=f"(y) : "f"(x)); return y;
}
__device__ __forceinline__ void arrive_release(int* p) {
    asm volatile("red.release.gpu.global.add.u32 [%0], 1;" :: "l"(p) : "memory");
}
__device__ __forceinline__ int ld_acq(const int* p) {
    int v; asm volatile("ld.acquire.gpu.global.b32 %0, [%1];" : "=r"(v) : "l"(p) : "memory");
    return v;
}
__device__ __forceinline__ u64 pack_hl(float v0, float v1) {
    u32 hi, lo;
    asm("cvt.rn.bf16x2.f32 %0, %1, %2;" : "=r"(hi) : "f"(v1), "f"(v0));
    float h0, h1;
    asm("{.reg .b16 x,y;\n\t mov.b32 {x,y}, %2;\n\t cvt.f32.bf16 %0, x;\n\t cvt.f32.bf16 %1, y;}"
        : "=f"(h0), "=f"(h1) : "r"(hi));
    asm("cvt.rn.bf16x2.f32 %0, %1, %2;" : "=r"(lo) : "f"(v1 - h1), "f"(v0 - h0));
    return ((u64)lo << 32) | (u64)hi;
}
__device__ __forceinline__ void mma_bf16(float& d0, float& d1, float& d2, float& d3,
                                         u32 a0, u32 a1, u32 a2, u32 a3,
                                         u32 b0, u32 b1) {
    asm volatile("mma.sync.aligned.m16n8k16.row.col.f32.bf16.bf16.f32 "
                 "{%0,%1,%2,%3}, {%4,%5,%6,%7}, {%8,%9}, {%0,%1,%2,%3};"
                 : "+f"(d0), "+f"(d1), "+f"(d2), "+f"(d3)
                 : "r"(a0), "r"(a1), "r"(a2), "r"(a3), "r"(b0), "r"(b1));
}

// =====================================================================
__global__ void reset_kernel() {
    int i = blockIdx.x * blockDim.x + threadIdx.x;
    if (i < NTIME * NROWT) g_bar[i * BARPAD] = 0;
}
__global__ void dummy_kernel() {}

// =====================================================================
// Phase 1: fin (t-major)
// =====================================================================
__global__ void __launch_bounds__(256)
fin_kernel(const int* __restrict__ w,
           const float* __restrict__ emb,
           const float* __restrict__ W_in,
           const float* __restrict__ b_in) {
    __shared__ int   widx[64];
    __shared__ float As[64 * 36];
    __shared__ float Bs[64 * 33];

    int tid = threadIdx.x;
    int tx = tid & 15, ty = tid >> 4;
    int bt0 = blockIdx.x * 64;
    int n0  = blockIdx.y * 64;

    if (tid < 64) {
        int rp = bt0 + tid;
        widx[tid] = w[((rp & 255) << 8) | (rp >> 8)];
    }
    __syncthreads();

    float acc[4][4] = {};
    for (int kc = 0; kc < NE; kc += 32) {
        for (int s = tid; s < 512; s += 256) {
            int row = s >> 3, q = (s & 7) << 2;
            float4 v = *(const float4*)&emb[widx[row] * NE + kc + q];
            *(float4*)&As[row * 36 + q] = v;
        }
        for (int s = tid; s < 512; s += 256) {
            int row = s >> 3, q = (s & 7) << 2;
            float4 v = *(const float4*)&W_in[(n0 + row) * FAN + kc + q];
            float* d = &Bs[row * 33 + q];
            d[0] = v.x; d[1] = v.y; d[2] = v.z; d[3] = v.w;
        }
        __syncthreads();
        #pragma unroll
        for (int k = 0; k < 32; ++k) {
            float a[4], b[4];
            #pragma unroll
            for (int i = 0; i < 4; ++i) a[i] = As[(ty + 16 * i) * 36 + k];
            #pragma unroll
            for (int j = 0; j < 4; ++j) b[j] = Bs[(tx + 16 * j) * 33 + k];
            #pragma unroll
            for (int i = 0; i < 4; ++i)
                #pragma unroll
                for (int j = 0; j < 4; ++j)
                    acc[i][j] = fmaf(a[i], b[j], acc[i][j]);
        }
        __syncthreads();
    }
    #pragma unroll
    for (int i = 0; i < 4; ++i) {
        int r = bt0 + ty + 16 * i;
        #pragma unroll
        for (int j = 0; j < 4; ++j) {
            int c = n0 + tx + 16 * j;
            g_fin[r * NS + c] = acc[i][j] + b_in[c];
        }
    }
}

// =====================================================================
// Phase 2: persistent recurrent kernel, tensor-core GEMM.
// Warp w = (cg = w&3: 16-col group, kh = w>>2: k-half). Each warp does a
// 16x16 tile over its k-half: per chunk 4 LDS.128 (perm-paired frags) +
// 6 bf16 MMAs (3-term hi/lo x n16). k-halves combined via smem reduction.
// A-replication 4x instead of 8x -> crossbar 2048 cyc/step (was 3072).
// =====================================================================
__global__ void __launch_bounds__(256, 1)
rnn_kernel(const float* __restrict__ W_in) {
    extern __shared__ u64 smq[];
    u64*   Bq  = smq;                    // [64][PITCH]  W_s packed (perm)
    u64*   Aq  = smq + 64 * PITCH;       // [16][PITCH]  state packed (perm)
    float* Red = (float*)(smq + 80 * PITCH);   // [4][32][8] k-half partials

    const int tid  = threadIdx.x;
    const int wrp  = tid >> 5;
    const int lane = tid & 31;
    const int g    = lane >> 2;          // 0..7
    const int tq   = lane & 3;           // 0..3
    const int cg   = wrp & 3;            // col group (16 cols)
    const int kh   = wrp >> 2;           // k-half
    const int rowtile = blockIdx.x >> 3;
    const int coltile = blockIdx.x & 7;
    const int rb0 = rowtile * 16;
    const int cb0 = coltile * 64;

    // pack W_s slice once (perm layout)
    for (int s = tid; s < 64 * 256; s += 256) {
        int n = s >> 8, p = s & 255;
        const float* wp = &W_in[(cb0 + n) * FAN + NE + 2 * p];
        Bq[n * PITCH + PERM(p)] = pack_hl(wp[0], wp[1]);
    }
    __syncthreads();

    const u64* arow0 = Aq + g * PITCH;
    const u64* arow1 = Aq + (g + 8) * PITCH;
    const u64* brow0 = Bq + (16 * cg + g) * PITCH;
    const u64* brow1 = Bq + (16 * cg + g + 8) * PITCH;

    const int r0 = rb0 + g, r1 = rb0 + g + 8;
    const int c0 = cb0 + 16 * cg + 2 * tq;     // first n8 group cols c0,c0+1
    const int c1 = c0 + 8;                     // second n8 group
    const int pg0 = c0 >> 1, pg1 = pg0 + 4;    // global k-pair indices
    const int kbase = kh * 16;                 // chunk base for this k-half

    const int srow = tid >> 4;                 // staging row 0..15
    const int sp0  = tid & 15;

    float* redp = &Red[(cg * 32 + lane) * 8];

    float2 f00, f01, f10, f11;
    if (kh == 0) {
        f00 = *(const float2*)&g_fin[r0 * NS + c0];
        f01 = *(const float2*)&g_fin[r0 * NS + c1];
        f10 = *(const float2*)&g_fin[r1 * NS + c0];
        f11 = *(const float2*)&g_fin[r1 * NS + c1];
    }

    for (int t = 0; t < NTIME; ++t) {
        float d0=0.f,d1=0.f,d2=0.f,d3=0.f,d4=0.f,d5=0.f,d6=0.f,d7=0.f;

        if (t > 0) {
            const int* bar = &g_bar[((t - 1) * NROWT + rowtile) * BARPAD];
            while (ld_acq(bar) < NCOLT) { }

            // stage packed state[t-1] into Aq (perm layout)
            const u64* src = &g_state_pk[(t - 1) & 1][(rb0 + srow) << 8];
            u64* dst = &Aq[srow * PITCH];
            #pragma unroll
            for (int j = 0; j < 16; ++j) {
                int idx = sp0 + 16 * j;
                dst[PERM(idx)] = __ldcg(&src[idx]);
            }
            __syncthreads();

            // GEMM: 16 chunks of k16 (this k-half)
            #pragma unroll
            for (int cc = 0; cc < 16; ++cc) {
                int off = 8 * (kbase + cc) + 2 * tq;
                ulonglong2 A0 = *(const ulonglong2*)(arow0 + off);
                ulonglong2 A1 = *(const ulonglong2*)(arow1 + off);
                ulonglong2 B0 = *(const ulonglong2*)(brow0 + off);
                ulonglong2 B1 = *(const ulonglong2*)(brow1 + off);
                u32 ah0 = (u32)A0.x, ah1 = (u32)A1.x, ah2 = (u32)A0.y, ah3 = (u32)A1.y;
                u32 al0 = (u32)(A0.x >> 32), al1 = (u32)(A1.x >> 32);
                u32 al2 = (u32)(A0.y >> 32), al3 = (u32)(A1.y >> 32);
                u32 bh0 = (u32)B0.x, bh1 = (u32)B0.y;
                u32 bl0 = (u32)(B0.x >> 32), bl1 = (u32)(B0.y >> 32);
                u32 ch0 = (u32)B1.x, ch1 = (u32)B1.y;
                u32 cl0 = (u32)(B1.x >> 32), cl1 = (u32)(B1.y >> 32);
                mma_bf16(d0,d1,d2,d3, ah0,ah1,ah2,ah3, bh0,bh1);
                mma_bf16(d0,d1,d2,d3, al0,al1,al2,al3, bh0,bh1);
                mma_bf16(d0,d1,d2,d3, ah0,ah1,ah2,ah3, bl0,bl1);
                mma_bf16(d4,d5,d6,d7, ah0,ah1,ah2,ah3, ch0,ch1);
                mma_bf16(d4,d5,d6,d7, al0,al1,al2,al3, ch0,ch1);
                mma_bf16(d4,d5,d6,d7, ah0,ah1,ah2,ah3, cl0,cl1);
            }

            // k-half reduction: kh=1 writes partials, kh=0 accumulates
            if (kh == 1) {
                redp[0]=d0; redp[1]=d1; redp[2]=d2; redp[3]=d3;
                redp[4]=d4; redp[5]=d5; redp[6]=d6; redp[7]=d7;
            }
            __syncthreads();
            if (kh == 0) {
                d0 += redp[0]; d1 += redp[1]; d2 += redp[2]; d3 += redp[3];
                d4 += redp[4]; d5 += redp[5]; d6 += redp[6]; d7 += redp[7];
            }
        }

        if (kh == 0) {
            float v0 = tanh_fast(d0 + f00.x), v1 = tanh_fast(d1 + f00.y);
            float v2 = tanh_fast(d2 + f10.x), v3 = tanh_fast(d3 + f10.y);
            float v4 = tanh_fast(d4 + f01.x), v5 = tanh_fast(d5 + f01.y);
            float v6 = tanh_fast(d6 + f11.x), v7 = tanh_fast(d7 + f11.y);

            const int sel = t & 1;
            g_state_pk[sel][(r0 << 8) + pg0] = pack_hl(v0, v1);
            g_state_pk[sel][(r1 << 8) + pg0] = pack_hl(v2, v3);
            g_state_pk[sel][(r0 << 8) + pg1] = pack_hl(v4, v5);
            g_state_pk[sel][(r1 << 8) + pg1] = pack_hl(v6, v7);

            // fp32 log (t-major, streaming; off the critical path)
            __stcs((float2*)&g_states[((unsigned)t * NBATCH + r0) * NS + c0],
                   make_float2(v0, v1));
            __stcs((float2*)&g_states[((unsigned)t * NBATCH + r1) * NS + c0],
                   make_float2(v2, v3));
            __stcs((float2*)&g_states[((unsigned)t * NBATCH + r0) * NS + c1],
                   make_float2(v4, v5));
            __stcs((float2*)&g_states[((unsigned)t * NBATCH + r1) * NS + c1],
                   make_float2(v6, v7));
        }
        __syncthreads();   // exchange STGs issued (w0-3) + Aq/Red reads done

        if (t + 1 < NTIME) {
            if (tid == 0)
                arrive_release(&g_bar[(t * NROWT + rowtile) * BARPAD]);
            if (kh == 0) {
                f00 = __ldcg((const float2*)&g_fin[((t + 1) * NBATCH + r0) * NS + c0]);
                f01 = __ldcg((const float2*)&g_fin[((t + 1) * NBATCH + r0) * NS + c1]);
                f10 = __ldcg((const float2*)&g_fin[((t + 1) * NBATCH + r1) * NS + c0]);
                f11 = __ldcg((const float2*)&g_fin[((t + 1) * NBATCH + r1) * NS + c1]);
            }
        }
    }
}

// =====================================================================
// Phase 3: y = states @ W_out^T + b_out   (states t-major)
// =====================================================================
__global__ void __launch_bounds__(256)
out_kernel(const float* __restrict__ W_out,
           const float* __restrict__ b_out,
           float* __restrict__ y) {
    __shared__ float As[64 * 36];
    __shared__ float Bs[64 * 33];
    __shared__ int   rowmap[64];

    int tid = threadIdx.x;
    int tx = tid & 15, ty = tid >> 4;
    int bt0 = blockIdx.x * 64;
    int a0  = blockIdx.y * 64;

    if (tid < 64) {
        int r = bt0 + tid;
        rowmap[tid] = ((r & 255) << 8) | (r >> 8);
    }
    __syncthreads();

    float acc[4][4] = {};
    for (int kc = 0; kc < NS; kc += 32) {
        for (int s = tid; s < 512; s += 256) {
            int row = s >> 3, q = (s & 7) << 2;
            float4 v = *(const float4*)&g_states[rowmap[row] * NS + kc + q];
            *(float4*)&As[row * 36 + q] = v;
        }
        for (int s = tid; s < 512; s += 256) {
            int row = s >> 3, q = (s & 7) << 2;
            float4 v = *(const float4*)&W_out[(a0 + row) * NS + kc + q];
            float* d = &Bs[row * 33 + q];
            d[0] = v.x; d[1] = v.y; d[2] = v.z; d[3] = v.w;
        }
        __syncthreads();
        #pragma unroll
        for (int k = 0; k < 32; ++k) {
            float a[4], b[4];
            #pragma unroll
            for (int i = 0; i < 4; ++i) a[i] = As[(ty + 16 * i) * 36 + k];
            #pragma unroll
            for (int j = 0; j < 4; ++j) b[j] = Bs[(tx + 16 * j) * 33 + k];
            #pragma unroll
            for (int i = 0; i < 4; ++i)
                #pragma unroll
                for (int j = 0; j < 4; ++j)
                    acc[i][j] = fmaf(a[i], b[j], acc[i][j]);
        }
        __syncthreads();
    }
    #pragma unroll
    for (int i = 0; i < 4; ++i) {
        int r = bt0 + ty + 16 * i;
        #pragma unroll
        for (int j = 0; j < 4; ++j) {
            int col = a0 + tx + 16 * j;
            y[r * NALPH + col] = acc[i][j] + b_out[col];
        }
    }
}

// =====================================================================
// launch: reset, fin, dummy, rnn, out  (rnn = 4th launch -> profiled)
// =====================================================================
extern "C" void kernel_launch(void* const* d_in, const int* in_sizes, int n_in,
                              void* d_out, int out_size) {
    const int*   w     = (const int*)  d_in[0];
    const float* emb   = (const float*)d_in[1];
    const float* W_in  = (const float*)d_in[2];
    const float* b_in  = (const float*)d_in[3];
    const float* W_out = (const float*)d_in[4];
    const float* b_out = (const float*)d_in[5];
    float* y = (float*)d_out;

    size_t rnn_smem = (size_t)80 * PITCH * sizeof(u64) + 4 * 32 * 8 * sizeof(float);
    cudaFuncSetAttribute(rnn_kernel,
                         cudaFuncAttributeMaxDynamicSharedMemorySize,
                         (int)rnn_smem);

    reset_kernel<<<(NTIME * NROWT + 255) / 256, 256>>>();
    fin_kernel<<<dim3(BT / 64, NS / 64), 256>>>(w, emb, W_in, b_in);
    dummy_kernel<<<1, 32>>>();
    rnn_kernel<<<128, 256, rnn_smem>>>(W_in);
    out_kernel<<<dim3(BT / 64, NALPH / 64), 256>>>(W_out, b_out, y);
}

// round 15
// speedup vs baseline: 2.1909x; 1.0839x over previous
#include <cuda_runtime.h>
#include <cstdint>

#define NBATCH 256
#define NTIME  256
#define NS     512
#define NE     128
#define NALPH  128
#define FAN    640
#define BT     (NBATCH * NTIME)

#define NROWT  16
#define NCOLT  8
#define BARPAD 32
#define PITCH  264   // rnn smem pitch (u64); 16B-chunks/row = 132 ≡ 4 mod 8
#define P2     72    // fin/out smem pitch (u64); 36 ≡ 4 mod 8

// fragment-pair permutation: k-pair p -> smem slot (pairs p, p+4 adjacent)
#define PERM(p) (((p) & 248) | (((p) & 3) << 1) | (((p) >> 2) & 1))

typedef unsigned long long u64;
typedef unsigned int u32;

// ---- scratch ----
__device__ float g_fin[BT * NS];              // fin[(t*NBATCH+b)*NS + n] fp32
__device__ u64   g_spk_log[BT * 256];         // packed states log (t-major)
__device__ u64   g_state_pk[2][NBATCH * 256]; // HOT packed exchange buffer
__device__ u64   g_emb_pk[NALPH * 64];        // packed emb   [128][64]
__device__ u64   g_wf_pk[NS * 64];            // packed W_f   [512][64]
__device__ u64   g_wout_pk[NALPH * 256];      // packed W_out [128][256]
__device__ int   g_bar[NTIME * NROWT * BARPAD];

// ---- helpers ----
__device__ __forceinline__ float tanh_fast(float x) {
    float y; asm("tanh.approx.f32 %0, %1;" : "=f"(y) : "f"(x)); return y;
}
__device__ __forceinline__ void arrive_release(int* p) {
    asm volatile("red.release.gpu.global.add.u32 [%0], 1;" :: "l"(p) : "memory");
}
__device__ __forceinline__ int ld_acq(const int* p) {
    int v; asm volatile("ld.acquire.gpu.global.b32 %0, [%1];" : "=r"(v) : "l"(p) : "memory");
    return v;
}
__device__ __forceinline__ void stcs_u64(u64* p, u64 v) {
    asm volatile("st.global.cs.b64 [%0], %1;" :: "l"(p), "l"(v) : "memory");
}
__device__ __forceinline__ u64 pack_hl(float v0, float v1) {
    u32 hi, lo;
    asm("cvt.rn.bf16x2.f32 %0, %1, %2;" : "=r"(hi) : "f"(v1), "f"(v0));
    float h0, h1;
    asm("{.reg .b16 x,y;\n\t mov.b32 {x,y}, %2;\n\t cvt.f32.bf16 %0, x;\n\t cvt.f32.bf16 %1, y;}"
        : "=f"(h0), "=f"(h1) : "r"(hi));
    asm("cvt.rn.bf16x2.f32 %0, %1, %2;" : "=r"(lo) : "f"(v1 - h1), "f"(v0 - h0));
    return ((u64)lo << 32) | (u64)hi;
}
__device__ __forceinline__ void mma_bf16(float& d0, float& d1, float& d2, float& d3,
                                         u32 a0, u32 a1, u32 a2, u32 a3,
                                         u32 b0, u32 b1) {
    asm volatile("mma.sync.aligned.m16n8k16.row.col.f32.bf16.bf16.f32 "
                 "{%0,%1,%2,%3}, {%4,%5,%6,%7}, {%8,%9}, {%0,%1,%2,%3};"
                 : "+f"(d0), "+f"(d1), "+f"(d2), "+f"(d3)
                 : "r"(a0), "r"(a1), "r"(a2), "r"(a3), "r"(b0), "r"(b1));
}

// 3-term hi/lo MMA over one k16 chunk for one n8 group
__device__ __forceinline__ void mma3(float* d,
                                     u32 ah0, u32 ah1, u32 ah2, u32 ah3,
                                     u32 al0, u32 al1, u32 al2, u32 al3,
                                     u64 bx, u64 by) {
    u32 bh0 = (u32)bx, bh1 = (u32)by;
    u32 bl0 = (u32)(bx >> 32), bl1 = (u32)(by >> 32);
    mma_bf16(d[0], d[1], d[2], d[3], ah0, ah1, ah2, ah3, bh0, bh1);
    mma_bf16(d[0], d[1], d[2], d[3], al0, al1, al2, al3, bh0, bh1);
    mma_bf16(d[0], d[1], d[2], d[3], ah0, ah1, ah2, ah3, bl0, bl1);
}

// =====================================================================
__global__ void reset_kernel() {
    int i = blockIdx.x * blockDim.x + threadIdx.x;
    if (i < NTIME * NROWT) g_bar[i * BARPAD] = 0;
}

// pre-pack emb, W_f, W_out into {hi,lo} u64 pairs
__global__ void prep_pack(const float* __restrict__ emb,
                          const float* __restrict__ W_in,
                          const float* __restrict__ W_out) {
    int i = blockIdx.x * blockDim.x + threadIdx.x;
    if (i < NALPH * 64) {
        int r = i >> 6, p = i & 63;
        g_emb_pk[i] = pack_hl(emb[r * NE + 2 * p], emb[r * NE + 2 * p + 1]);
    } else if (i < NALPH * 64 + NS * 64) {
        int j = i - NALPH * 64, n = j >> 6, p = j & 63;
        g_wf_pk[j] = pack_hl(W_in[n * FAN + 2 * p], W_in[n * FAN + 2 * p + 1]);
    } else if (i < NALPH * 64 + NS * 64 + NALPH * 256) {
        int j = i - NALPH * 64 - NS * 64, a = j >> 8, p = j & 255;
        g_wout_pk[j] = pack_hl(W_out[a * NS + 2 * p], W_out[a * NS + 2 * p + 1]);
    }
}

// =====================================================================
// Phase 1: fin via tensor cores.  64(bt) x 64(n) CTA tile, K=128.
// =====================================================================
__global__ void __launch_bounds__(256)
fin_kernel_mma(const int* __restrict__ w,
               const float* __restrict__ b_in) {
    extern __shared__ u64 smf[];
    u64* Aq = smf;             // [64][P2]
    u64* Bq = smf + 64 * P2;   // [64][P2]
    __shared__ int widx[64];

    const int tid  = threadIdx.x;
    const int lane = tid & 31, wrp = tid >> 5;
    const int g    = lane >> 2, tq = lane & 3;
    const int rg   = wrp & 3, ch = wrp >> 2;
    const int bt0  = blockIdx.x * 64;     // t-major row base
    const int n0   = blockIdx.y * 64;

    if (tid < 64) {
        int rp = bt0 + tid;                            // t*256 + b
        widx[tid] = w[((rp & 255) << 8) | (rp >> 8)];  // w[b*256+t]
    }
    __syncthreads();

    for (int s = tid; s < 64 * 64; s += 256) {
        int row = s >> 6, p = s & 63;
        Aq[row * P2 + PERM(p)] = g_emb_pk[widx[row] * 64 + p];
    }
    for (int s = tid; s < 64 * 64; s += 256) {
        int row = s >> 6, p = s & 63;
        Bq[row * P2 + PERM(p)] = g_wf_pk[(n0 + row) * 64 + p];
    }
    __syncthreads();

    const u64* ar0 = Aq + (rg * 16 + g) * P2;
    const u64* ar1 = ar0 + 8 * P2;
    const u64* br0 = Bq + (ch * 32 + g) * P2;
    const u64* br1 = br0 + 8 * P2;
    const u64* br2 = br0 + 16 * P2;
    const u64* br3 = br0 + 24 * P2;

    float d[4][4] = {};
    #pragma unroll
    for (int kk = 0; kk < 8; ++kk) {
        int off = 8 * kk + 2 * tq;
        ulonglong2 A0 = *(const ulonglong2*)(ar0 + off);
        ulonglong2 A1 = *(const ulonglong2*)(ar1 + off);
        u32 ah0=(u32)A0.x, ah1=(u32)A1.x, ah2=(u32)A0.y, ah3=(u32)A1.y;
        u32 al0=(u32)(A0.x>>32), al1=(u32)(A1.x>>32);
        u32 al2=(u32)(A0.y>>32), al3=(u32)(A1.y>>32);
        ulonglong2 B0 = *(const ulonglong2*)(br0 + off);
        ulonglong2 B1 = *(const ulonglong2*)(br1 + off);
        ulonglong2 B2 = *(const ulonglong2*)(br2 + off);
        ulonglong2 B3 = *(const ulonglong2*)(br3 + off);
        mma3(d[0], ah0,ah1,ah2,ah3, al0,al1,al2,al3, B0.x, B0.y);
        mma3(d[1], ah0,ah1,ah2,ah3, al0,al1,al2,al3, B1.x, B1.y);
        mma3(d[2], ah0,ah1,ah2,ah3, al0,al1,al2,al3, B2.x, B2.y);
        mma3(d[3], ah0,ah1,ah2,ah3, al0,al1,al2,al3, B3.x, B3.y);
    }

    int row0 = bt0 + rg * 16 + g, row1 = row0 + 8;
    #pragma unroll
    for (int j = 0; j < 4; ++j) {
        int col = n0 + ch * 32 + 8 * j + 2 * tq;
        float2 bi = *(const float2*)&b_in[col];
        *(float2*)&g_fin[row0 * NS + col] = make_float2(d[j][0] + bi.x, d[j][1] + bi.y);
        *(float2*)&g_fin[row1 * NS + col] = make_float2(d[j][2] + bi.x, d[j][3] + bi.y);
    }
}

// =====================================================================
// Phase 2: persistent recurrent kernel (R14, unchanged math).
// Only delta: logs PACKED states (g_spk_log) instead of fp32.
// =====================================================================
__global__ void __launch_bounds__(256, 1)
rnn_kernel(const float* __restrict__ W_in) {
    extern __shared__ u64 smq[];
    u64*   Bq  = smq;                          // [64][PITCH]
    u64*   Aq  = smq + 64 * PITCH;             // [16][PITCH]
    float* Red = (float*)(smq + 80 * PITCH);   // [4][32][8]

    const int tid  = threadIdx.x;
    const int wrp  = tid >> 5;
    const int lane = tid & 31;
    const int g    = lane >> 2;
    const int tq   = lane & 3;
    const int cg   = wrp & 3;
    const int kh   = wrp >> 2;
    const int rowtile = blockIdx.x >> 3;
    const int coltile = blockIdx.x & 7;
    const int rb0 = rowtile * 16;
    const int cb0 = coltile * 64;

    for (int s = tid; s < 64 * 256; s += 256) {
        int n = s >> 8, p = s & 255;
        const float* wp = &W_in[(cb0 + n) * FAN + NE + 2 * p];
        Bq[n * PITCH + PERM(p)] = pack_hl(wp[0], wp[1]);
    }
    __syncthreads();

    const u64* arow0 = Aq + g * PITCH;
    const u64* arow1 = Aq + (g + 8) * PITCH;
    const u64* brow0 = Bq + (16 * cg + g) * PITCH;
    const u64* brow1 = Bq + (16 * cg + g + 8) * PITCH;

    const int r0 = rb0 + g, r1 = rb0 + g + 8;
    const int c0 = cb0 + 16 * cg + 2 * tq;
    const int c1 = c0 + 8;
    const int pg0 = c0 >> 1, pg1 = pg0 + 4;
    const int kbase = kh * 16;

    const int srow = tid >> 4;
    const int sp0  = tid & 15;

    float* redp = &Red[(cg * 32 + lane) * 8];

    float2 f00, f01, f10, f11;
    if (kh == 0) {
        f00 = *(const float2*)&g_fin[r0 * NS + c0];
        f01 = *(const float2*)&g_fin[r0 * NS + c1];
        f10 = *(const float2*)&g_fin[r1 * NS + c0];
        f11 = *(const float2*)&g_fin[r1 * NS + c1];
    }

    for (int t = 0; t < NTIME; ++t) {
        float d0=0.f,d1=0.f,d2=0.f,d3=0.f,d4=0.f,d5=0.f,d6=0.f,d7=0.f;

        if (t > 0) {
            const int* bar = &g_bar[((t - 1) * NROWT + rowtile) * BARPAD];
            while (ld_acq(bar) < NCOLT) { }

            const u64* src = &g_state_pk[(t - 1) & 1][(rb0 + srow) << 8];
            u64* dst = &Aq[srow * PITCH];
            #pragma unroll
            for (int j = 0; j < 16; ++j) {
                int idx = sp0 + 16 * j;
                dst[PERM(idx)] = __ldcg(&src[idx]);
            }
            __syncthreads();

            #pragma unroll
            for (int cc = 0; cc < 16; ++cc) {
                int off = 8 * (kbase + cc) + 2 * tq;
                ulonglong2 A0 = *(const ulonglong2*)(arow0 + off);
                ulonglong2 A1 = *(const ulonglong2*)(arow1 + off);
                ulonglong2 B0 = *(const ulonglong2*)(brow0 + off);
                ulonglong2 B1 = *(const ulonglong2*)(brow1 + off);
                u32 ah0 = (u32)A0.x, ah1 = (u32)A1.x, ah2 = (u32)A0.y, ah3 = (u32)A1.y;
                u32 al0 = (u32)(A0.x >> 32), al1 = (u32)(A1.x >> 32);
                u32 al2 = (u32)(A0.y >> 32), al3 = (u32)(A1.y >> 32);
                u32 bh0 = (u32)B0.x, bh1 = (u32)B0.y;
                u32 bl0 = (u32)(B0.x >> 32), bl1 = (u32)(B0.y >> 32);
                u32 ch0 = (u32)B1.x, ch1 = (u32)B1.y;
                u32 cl0 = (u32)(B1.x >> 32), cl1 = (u32)(B1.y >> 32);
                mma_bf16(d0,d1,d2,d3, ah0,ah1,ah2,ah3, bh0,bh1);
                mma_bf16(d0,d1,d2,d3, al0,al1,al2,al3, bh0,bh1);
                mma_bf16(d0,d1,d2,d3, ah0,ah1,ah2,ah3, bl0,bl1);
                mma_bf16(d4,d5,d6,d7, ah0,ah1,ah2,ah3, ch0,ch1);
                mma_bf16(d4,d5,d6,d7, al0,al1,al2,al3, ch0,ch1);
                mma_bf16(d4,d5,d6,d7, ah0,ah1,ah2,ah3, cl0,cl1);
            }

            if (kh == 1) {
                redp[0]=d0; redp[1]=d1; redp[2]=d2; redp[3]=d3;
                redp[4]=d4; redp[5]=d5; redp[6]=d6; redp[7]=d7;
            }
            __syncthreads();
            if (kh == 0) {
                d0 += redp[0]; d1 += redp[1]; d2 += redp[2]; d3 += redp[3];
                d4 += redp[4]; d5 += redp[5]; d6 += redp[6]; d7 += redp[7];
            }
        }

        if (kh == 0) {
            float v0 = tanh_fast(d0 + f00.x), v1 = tanh_fast(d1 + f00.y);
            float v2 = tanh_fast(d2 + f10.x), v3 = tanh_fast(d3 + f10.y);
            float v4 = tanh_fast(d4 + f01.x), v5 = tanh_fast(d5 + f01.y);
            float v6 = tanh_fast(d6 + f11.x), v7 = tanh_fast(d7 + f11.y);

            u64 pk00 = pack_hl(v0, v1), pk10 = pack_hl(v2, v3);
            u64 pk01 = pack_hl(v4, v5), pk11 = pack_hl(v6, v7);

            const int sel = t & 1;
            g_state_pk[sel][(r0 << 8) + pg0] = pk00;
            g_state_pk[sel][(r1 << 8) + pg0] = pk10;
            g_state_pk[sel][(r0 << 8) + pg1] = pk01;
            g_state_pk[sel][(r1 << 8) + pg1] = pk11;

            // packed log (t-major; off the critical path)
            stcs_u64(&g_spk_log[(((unsigned)t * NBATCH + r0) << 8) + pg0], pk00);
            stcs_u64(&g_spk_log[(((unsigned)t * NBATCH + r1) << 8) + pg0], pk10);
            stcs_u64(&g_spk_log[(((unsigned)t * NBATCH + r0) << 8) + pg1], pk01);
            stcs_u64(&g_spk_log[(((unsigned)t * NBATCH + r1) << 8) + pg1], pk11);
        }
        __syncthreads();

        if (t + 1 < NTIME) {
            if (tid == 0)
                arrive_release(&g_bar[(t * NROWT + rowtile) * BARPAD]);
            if (kh == 0) {
                f00 = __ldcg((const float2*)&g_fin[((t + 1) * NBATCH + r0) * NS + c0]);
                f01 = __ldcg((const float2*)&g_fin[((t + 1) * NBATCH + r0) * NS + c1]);
                f10 = __ldcg((const float2*)&g_fin[((t + 1) * NBATCH + r1) * NS + c0]);
                f11 = __ldcg((const float2*)&g_fin[((t + 1) * NBATCH + r1) * NS + c1]);
            }
        }
    }
}

// =====================================================================
// Phase 3: y via tensor cores.  64(bt) x 64(a) CTA tile, K=512 (4 chunks).
// A = packed states log (t-major), B = packed W_out.
// =====================================================================
__global__ void __launch_bounds__(256)
out_kernel_mma(const float* __restrict__ b_out,
               float* __restrict__ y) {
    extern __shared__ u64 smo[];
    u64* Aq = smo;             // [64][P2]
    u64* Bq = smo + 64 * P2;   // [64][P2]
    __shared__ int rowmap[64];

    const int tid  = threadIdx.x;
    const int lane = tid & 31, wrp = tid >> 5;
    const int g    = lane >> 2, tq = lane & 3;
    const int rg   = wrp & 3, ch = wrp >> 2;
    const int bt0  = blockIdx.x * 64;     // output rows (b-major)
    const int a0   = blockIdx.y * 64;

    if (tid < 64) {
        int r = bt0 + tid;
        rowmap[tid] = ((r & 255) << 8) | (r >> 8);   // t-major log row
    }
    __syncthreads();

    const u64* ar0 = Aq + (rg * 16 + g) * P2;
    const u64* ar1 = ar0 + 8 * P2;
    const u64* br0 = Bq + (ch * 32 + g) * P2;
    const u64* br1 = br0 + 8 * P2;
    const u64* br2 = br0 + 16 * P2;
    const u64* br3 = br0 + 24 * P2;

    float d[4][4] = {};

    for (int kc = 0; kc < 4; ++kc) {
        for (int s = tid; s < 64 * 64; s += 256) {
            int row = s >> 6, p = s & 63;
            Aq[row * P2 + PERM(p)] =
                __ldcg(&g_spk_log[rowmap[row] * 256 + 64 * kc + p]);
        }
        for (int s = tid; s < 64 * 64; s += 256) {
            int row = s >> 6, p = s & 63;
            Bq[row * P2 + PERM(p)] = g_wout_pk[(a0 + row) * 256 + 64 * kc + p];
        }
        __syncthreads();

        #pragma unroll
        for (int kk = 0; kk < 8; ++kk) {
            int off = 8 * kk + 2 * tq;
            ulonglong2 A0 = *(const ulonglong2*)(ar0 + off);
            ulonglong2 A1 = *(const ulonglong2*)(ar1 + off);
            u32 ah0=(u32)A0.x, ah1=(u32)A1.x, ah2=(u32)A0.y, ah3=(u32)A1.y;
            u32 al0=(u32)(A0.x>>32), al1=(u32)(A1.x>>32);
            u32 al2=(u32)(A0.y>>32), al3=(u32)(A1.y>>32);
            ulonglong2 B0 = *(const ulonglong2*)(br0 + off);
            ulonglong2 B1 = *(const ulonglong2*)(br1 + off);
            ulonglong2 B2 = *(const ulonglong2*)(br2 + off);
            ulonglong2 B3 = *(const ulonglong2*)(br3 + off);
            mma3(d[0], ah0,ah1,ah2,ah3, al0,al1,al2,al3, B0.x, B0.y);
            mma3(d[1], ah0,ah1,ah2,ah3, al0,al1,al2,al3, B1.x, B1.y);
            mma3(d[2], ah0,ah1,ah2,ah3, al0,al1,al2,al3, B2.x, B2.y);
            mma3(d[3], ah0,ah1,ah2,ah3, al0,al1,al2,al3, B3.x, B3.y);
        }
        __syncthreads();
    }

    int row0 = bt0 + rg * 16 + g, row1 = row0 + 8;
    #pragma unroll
    for (int j = 0; j < 4; ++j) {
        int col = a0 + ch * 32 + 8 * j + 2 * tq;
        float2 bo = *(const float2*)&b_out[col];
        *(float2*)&y[row0 * NALPH + col] = make_float2(d[j][0] + bo.x, d[j][1] + bo.y);
        *(float2*)&y[row1 * NALPH + col] = make_float2(d[j][2] + bo.x, d[j][3] + bo.y);
    }
}

// =====================================================================
// launch: reset, prep, fin, rnn, out   (rnn = 4th launch -> profiled)
// =====================================================================
extern "C" void kernel_launch(void* const* d_in, const int* in_sizes, int n_in,
                              void* d_out, int out_size) {
    const int*   w     = (const int*)  d_in[0];
    const float* emb   = (const float*)d_in[1];
    const float* W_in  = (const float*)d_in[2];
    const float* b_in  = (const float*)d_in[3];
    const float* W_out = (const float*)d_in[4];
    const float* b_out = (const float*)d_in[5];
    float* y = (float*)d_out;

    size_t rnn_smem = (size_t)80 * PITCH * sizeof(u64) + 4 * 32 * 8 * sizeof(float);
    size_t gem_smem = (size_t)128 * P2 * sizeof(u64);   // 72 KB
    cudaFuncSetAttribute(rnn_kernel,
                         cudaFuncAttributeMaxDynamicSharedMemorySize, (int)rnn_smem);
    cudaFuncSetAttribute(fin_kernel_mma,
                         cudaFuncAttributeMaxDynamicSharedMemorySize, (int)gem_smem);
    cudaFuncSetAttribute(out_kernel_mma,
                         cudaFuncAttributeMaxDynamicSharedMemorySize, (int)gem_smem);

    reset_kernel<<<(NTIME * NROWT + 255) / 256, 256>>>();
    prep_pack<<<(NALPH * 64 + NS * 64 + NALPH * 256 + 255) / 256, 256>>>(emb, W_in, W_out);
    fin_kernel_mma<<<dim3(BT / 64, NS / 64), 256, gem_smem>>>(w, b_in);
    rnn_kernel<<<128, 256, rnn_smem>>>(W_in);
    out_kernel_mma<<<dim3(BT / 64, NALPH / 64), 256, gem_smem>>>(b_out, y);
}